// round 2
// baseline (speedup 1.0000x reference)
#include <cuda_runtime.h>
#include <cuda_bf16.h>

#define DM 768
#define NH 12
#define DK 64
#define NB 2
#define SL 2048
#define MR (NB*SL)     // 4096
#define BH (NB*NH)     // 24

// Scratch (allocation-free requirement): ~48MB static device arrays.
__device__ float g_Qh[(size_t)BH*SL*DK];
__device__ float g_Kh[(size_t)BH*SL*DK];
__device__ float g_Vh[(size_t)BH*SL*DK];
__device__ float g_attn[(size_t)MR*DM];

// ---------------------------------------------------------------------------
// GEMM: C[M=4096, N=768] = A[M,768] @ W[768,768] + bias
// 64x64 tile, K-tile 16, 256 threads, 4x4 microtile per thread.
// head_layout=1: scatter into per-head layout [(b*NH+h), s, d]
// ---------------------------------------------------------------------------
__global__ __launch_bounds__(256) void gemm_bias(
    const float* __restrict__ A, const float* __restrict__ W,
    const float* __restrict__ bias, float* __restrict__ C, int head_layout)
{
    __shared__ float As[16][64];   // [k][m]
    __shared__ float Ws[16][64];   // [k][n]

    int tid = threadIdx.x;
    int tx = tid & 15, ty = tid >> 4;
    int mBase = blockIdx.y << 6;
    int nBase = blockIdx.x << 6;

    float acc[4][4];
    #pragma unroll
    for (int i = 0; i < 4; i++)
        #pragma unroll
        for (int j = 0; j < 4; j++) acc[i][j] = 0.f;

    for (int k0 = 0; k0 < DM; k0 += 16) {
        // Load A tile (64 rows x 16 k), float4 along k per thread.
        {
            int m  = tid >> 2;
            int kq = (tid & 3) << 2;
            float4 av = *reinterpret_cast<const float4*>(
                A + (size_t)(mBase + m) * DM + k0 + kq);
            As[kq + 0][m] = av.x; As[kq + 1][m] = av.y;
            As[kq + 2][m] = av.z; As[kq + 3][m] = av.w;
        }
        // Load W tile (16 k x 64 n), coalesced along n.
        #pragma unroll
        for (int r = 0; r < 4; r++) {
            int lin = tid + (r << 8);
            int kk = lin >> 6, n = lin & 63;
            Ws[kk][n] = W[(size_t)(k0 + kk) * DM + nBase + n];
        }
        __syncthreads();

        #pragma unroll
        for (int kk = 0; kk < 16; kk++) {
            float a[4], w[4];
            #pragma unroll
            for (int i = 0; i < 4; i++) a[i] = As[kk][ty + (i << 4)];
            #pragma unroll
            for (int j = 0; j < 4; j++) w[j] = Ws[kk][tx + (j << 4)];
            #pragma unroll
            for (int i = 0; i < 4; i++)
                #pragma unroll
                for (int j = 0; j < 4; j++)
                    acc[i][j] += a[i] * w[j];
        }
        __syncthreads();
    }

    #pragma unroll
    for (int i = 0; i < 4; i++) {
        #pragma unroll
        for (int j = 0; j < 4; j++) {
            int mm = mBase + ty + (i << 4);
            int nn = nBase + tx + (j << 4);
            float v = acc[i][j] + bias[nn];
            if (head_layout) {
                int b = mm >> 11;           // / SL
                int s = mm & (SL - 1);
                int h = nn >> 6;            // / DK
                int d = nn & 63;
                g_Qh[0]; // no-op to keep symbols referenced paths identical
                C[(((size_t)(b * NH + h)) * SL + s) * DK + d] = v;
            } else {
                C[(size_t)mm * DM + nn] = v;
            }
        }
    }
}

// ---------------------------------------------------------------------------
// Flash attention, fp32. Block = 256 threads = 8 warps; warp owns 4 q-rows;
// block owns 32 q-rows. K/V tiles of 64 keys staged in shared (stride 65 ->
// conflict-free per-lane column access). Online softmax in registers.
// P broadcast to lanes via __shfl_sync (saves 16KB smem).
// ---------------------------------------------------------------------------
__global__ __launch_bounds__(256) void attn_kernel(
    const float* __restrict__ Qh, const float* __restrict__ Kh,
    const float* __restrict__ Vh, const int* __restrict__ mask,
    float* __restrict__ outp)
{
    __shared__ float sK[64][65];
    __shared__ float sV[64][65];
    __shared__ float sQ[32][64];

    int bh = blockIdx.y;
    int b = bh / NH;
    int h = bh - b * NH;
    int tid = threadIdx.x;
    int warp = tid >> 5, lane = tid & 31;
    int rowBase = blockIdx.x << 5;     // first q-row of this block

    const float* qbase = Qh + ((size_t)bh * SL + rowBase) * DK;
    const float* kbase = Kh + (size_t)bh * SL * DK;
    const float* vbase = Vh + (size_t)bh * SL * DK;
    const int*   mrow  = mask + b * SL;

    // Load 32 q-rows (2048 floats) into shared.
    #pragma unroll
    for (int r = 0; r < 2; r++) {
        int lin = tid + (r << 8);       // 0..511 float4s
        int row = lin >> 4;
        int c4  = (lin & 15) << 2;
        float4 v = *reinterpret_cast<const float4*>(qbase + (size_t)row * DK + c4);
        sQ[row][c4] = v.x; sQ[row][c4+1] = v.y; sQ[row][c4+2] = v.z; sQ[row][c4+3] = v.w;
    }

    float m_i[4], l_i[4], a0[4], a1[4];
    #pragma unroll
    for (int r = 0; r < 4; r++) { m_i[r] = -1e30f; l_i[r] = 0.f; a0[r] = 0.f; a1[r] = 0.f; }
    int wq = warp << 2;   // local row base of this warp

    for (int kt = 0; kt < SL; kt += 64) {
        __syncthreads();
        // Stage K and V tiles (64 keys x 64 dims each).
        #pragma unroll
        for (int r = 0; r < 4; r++) {
            int lin = tid + (r << 8);
            int row = lin >> 4;
            int c4  = (lin & 15) << 2;
            float4 kv = *reinterpret_cast<const float4*>(kbase + (size_t)(kt + row) * DK + c4);
            sK[row][c4] = kv.x; sK[row][c4+1] = kv.y; sK[row][c4+2] = kv.z; sK[row][c4+3] = kv.w;
            float4 vv = *reinterpret_cast<const float4*>(vbase + (size_t)(kt + row) * DK + c4);
            sV[row][c4] = vv.x; sV[row][c4+1] = vv.y; sV[row][c4+2] = vv.z; sV[row][c4+3] = vv.w;
        }
        __syncthreads();

        // Scores: lane owns keys j1=lane, j2=lane+32 for 4 rows.
        float s1[4] = {0.f,0.f,0.f,0.f}, s2[4] = {0.f,0.f,0.f,0.f};
        #pragma unroll 16
        for (int d = 0; d < 64; d++) {
            float k1 = sK[lane][d];
            float k2 = sK[lane + 32][d];
            #pragma unroll
            for (int r = 0; r < 4; r++) {
                float qd = sQ[wq + r][d];
                s1[r] += qd * k1;
                s2[r] += qd * k2;
            }
        }
        int mk1 = mrow[kt + lane];
        int mk2 = mrow[kt + lane + 32];

        // Online softmax per row.
        #pragma unroll
        for (int r = 0; r < 4; r++) {
            float v1 = mk1 ? s1[r] * 0.125f : -1e9f;
            float v2 = mk2 ? s2[r] * 0.125f : -1e9f;
            float tmax = fmaxf(v1, v2);
            #pragma unroll
            for (int o = 16; o; o >>= 1)
                tmax = fmaxf(tmax, __shfl_xor_sync(0xffffffffu, tmax, o));
            float nm   = fmaxf(m_i[r], tmax);
            float corr = __expf(m_i[r] - nm);
            float p1 = __expf(v1 - nm);
            float p2 = __expf(v2 - nm);
            float ps = p1 + p2;
            #pragma unroll
            for (int o = 16; o; o >>= 1)
                ps += __shfl_xor_sync(0xffffffffu, ps, o);
            l_i[r] = l_i[r] * corr + ps;
            a0[r] *= corr; a1[r] *= corr;
            m_i[r] = nm;
            s1[r] = p1; s2[r] = p2;     // reuse as P values
        }

        // PV: lane owns out dims d=lane, d=lane+32. P broadcast via shuffle.
        #pragma unroll 8
        for (int j = 0; j < 32; j++) {
            float v1 = sV[j][lane];
            float v2 = sV[j][lane + 32];
            #pragma unroll
            for (int r = 0; r < 4; r++) {
                float p = __shfl_sync(0xffffffffu, s1[r], j);
                a0[r] += p * v1;
                a1[r] += p * v2;
            }
        }
        #pragma unroll 8
        for (int j = 0; j < 32; j++) {
            float v1 = sV[j + 32][lane];
            float v2 = sV[j + 32][lane + 32];
            #pragma unroll
            for (int r = 0; r < 4; r++) {
                float p = __shfl_sync(0xffffffffu, s2[r], j);
                a0[r] += p * v1;
                a1[r] += p * v2;
            }
        }
    }

    // Write [B, S, DM] with head offset h*DK.
    #pragma unroll
    for (int r = 0; r < 4; r++) {
        float inv = 1.f / l_i[r];
        int s = rowBase + wq + r;
        size_t o = ((size_t)b * SL + s) * DM + (size_t)h * DK;
        outp[o + lane]      = a0[r] * inv;
        outp[o + lane + 32] = a1[r] * inv;
    }
}

// ---------------------------------------------------------------------------
extern "C" void kernel_launch(void* const* d_in, const int* in_sizes, int n_in,
                              void* d_out, int out_size)
{
    const float* q  = (const float*)d_in[0];
    const float* k  = (const float*)d_in[1];
    const float* v  = (const float*)d_in[2];
    const float* Wq = (const float*)d_in[3];
    const float* bq = (const float*)d_in[4];
    const float* Wk = (const float*)d_in[5];
    const float* bk = (const float*)d_in[6];
    const float* Wv = (const float*)d_in[7];
    const float* bv = (const float*)d_in[8];
    const float* Wo = (const float*)d_in[9];
    const float* bo = (const float*)d_in[10];
    const int* mask = (const int*)d_in[11];

    float *Qh, *Kh, *Vh, *attn;
    cudaGetSymbolAddress((void**)&Qh,   g_Qh);
    cudaGetSymbolAddress((void**)&Kh,   g_Kh);
    cudaGetSymbolAddress((void**)&Vh,   g_Vh);
    cudaGetSymbolAddress((void**)&attn, g_attn);

    dim3 gg(DM / 64, MR / 64);   // (12, 64)
    gemm_bias<<<gg, 256>>>(q, Wq, bq, Qh, 1);
    gemm_bias<<<gg, 256>>>(k, Wk, bk, Kh, 1);
    gemm_bias<<<gg, 256>>>(v, Wv, bv, Vh, 1);

    attn_kernel<<<dim3(SL / 32, BH), 256>>>(Qh, Kh, Vh, mask, attn);

    gemm_bias<<<gg, 256>>>(attn, Wo, bo, (float*)d_out, 0);
}

// round 5
// speedup vs baseline: 3.3770x; 3.3770x over previous
#include <cuda_runtime.h>
#include <cuda_bf16.h>
#include <cstdint>

#define DM 768
#define NH 12
#define DK 64
#define NB 2
#define SL 2048
#define MR (NB*SL)     // 4096
#define BH (NB*NH)     // 24

// Scratch (allocation-free requirement): static device arrays.
__device__ float g_Qh[(size_t)BH*SL*DK];
__device__ float g_Kh[(size_t)BH*SL*DK];
__device__ float g_Vh[(size_t)BH*SL*DK];
__device__ float g_attn[(size_t)MR*DM];

// ---------------------------------------------------------------------------
// TF32 helpers
// ---------------------------------------------------------------------------
__device__ __forceinline__ uint32_t f2tf(float x) {
    uint32_t r; asm("cvt.rna.tf32.f32 %0, %1;" : "=r"(r) : "f"(x)); return r;
}
__device__ __forceinline__ float f2tf_f(float x) {
    return __uint_as_float(f2tf(x));
}
__device__ __forceinline__ void mma_tf32(float c[4],
    uint32_t a0, uint32_t a1, uint32_t a2, uint32_t a3,
    uint32_t b0, uint32_t b1)
{
    asm volatile(
        "mma.sync.aligned.m16n8k8.row.col.f32.tf32.tf32.f32 "
        "{%0,%1,%2,%3}, {%4,%5,%6,%7}, {%8,%9}, {%0,%1,%2,%3};"
        : "+f"(c[0]), "+f"(c[1]), "+f"(c[2]), "+f"(c[3])
        : "r"(a0), "r"(a1), "r"(a2), "r"(a3), "r"(b0), "r"(b1));
}

// ---------------------------------------------------------------------------
// GEMM: C[M,768] = (A[M,768] @ W[768,768] + bias) * scale
// Block tile 128x64, kTile 32, 256 threads (8 warps, 4x2 of 32x32 warp tiles).
// Padded smem strides chosen so every mma fragment LDS is conflict-free.
// ---------------------------------------------------------------------------
#define GA_ST 36
#define GW_ST 72

__global__ __launch_bounds__(256, 2) void gemm_tc(
    const float* __restrict__ A, const float* __restrict__ W,
    const float* __restrict__ bias, float* __restrict__ C,
    int head_layout, float scale)
{
    __shared__ float sA[128 * GA_ST];
    __shared__ float sW[32 * GW_ST];

    int tid  = threadIdx.x;
    int lane = tid & 31, warp = tid >> 5;
    int wm = warp & 3, wn = warp >> 2;        // 4 m-tiles x 2 n-tiles of 32
    int mBase = blockIdx.y << 7;
    int nBase = blockIdx.x << 6;

    float acc[2][4][4];
    #pragma unroll
    for (int mi = 0; mi < 2; mi++)
        #pragma unroll
        for (int ni = 0; ni < 4; ni++)
            #pragma unroll
            for (int r = 0; r < 4; r++) acc[mi][ni][r] = 0.f;

    for (int k0 = 0; k0 < DM; k0 += 32) {
        // A tile 128x32
        #pragma unroll
        for (int i = 0; i < 4; i++) {
            int idx = tid + (i << 8);
            int row = idx >> 3, kq = (idx & 7) << 2;
            float4 v = *reinterpret_cast<const float4*>(
                A + (size_t)(mBase + row) * DM + k0 + kq);
            float4 t = make_float4(f2tf_f(v.x), f2tf_f(v.y), f2tf_f(v.z), f2tf_f(v.w));
            *reinterpret_cast<float4*>(sA + row * GA_ST + kq) = t;
        }
        // W tile 32x64
        #pragma unroll
        for (int i = 0; i < 2; i++) {
            int idx = tid + (i << 8);
            int row = idx >> 4, nq = (idx & 15) << 2;
            float4 v = *reinterpret_cast<const float4*>(
                W + (size_t)(k0 + row) * DM + nBase + nq);
            float4 t = make_float4(f2tf_f(v.x), f2tf_f(v.y), f2tf_f(v.z), f2tf_f(v.w));
            *reinterpret_cast<float4*>(sW + row * GW_ST + nq) = t;
        }
        __syncthreads();

        #pragma unroll
        for (int ks = 0; ks < 4; ks++) {
            int kk = (ks << 3) + (lane & 3);
            uint32_t a[2][4], b[4][2];
            #pragma unroll
            for (int mi = 0; mi < 2; mi++) {
                int r = wm * 32 + mi * 16 + (lane >> 2);
                a[mi][0] = __float_as_uint(sA[r * GA_ST + kk]);
                a[mi][1] = __float_as_uint(sA[(r + 8) * GA_ST + kk]);
                a[mi][2] = __float_as_uint(sA[r * GA_ST + kk + 4]);
                a[mi][3] = __float_as_uint(sA[(r + 8) * GA_ST + kk + 4]);
            }
            #pragma unroll
            for (int ni = 0; ni < 4; ni++) {
                int nn = wn * 32 + ni * 8 + (lane >> 2);
                b[ni][0] = __float_as_uint(sW[kk * GW_ST + nn]);
                b[ni][1] = __float_as_uint(sW[(kk + 4) * GW_ST + nn]);
            }
            #pragma unroll
            for (int mi = 0; mi < 2; mi++)
                #pragma unroll
                for (int ni = 0; ni < 4; ni++)
                    mma_tf32(acc[mi][ni], a[mi][0], a[mi][1], a[mi][2], a[mi][3],
                             b[ni][0], b[ni][1]);
        }
        __syncthreads();
    }

    // Epilogue
    #pragma unroll
    for (int mi = 0; mi < 2; mi++) {
        int row = mBase + wm * 32 + mi * 16 + (lane >> 2);
        #pragma unroll
        for (int ni = 0; ni < 4; ni++) {
            int col = nBase + wn * 32 + ni * 8 + 2 * (lane & 3);
            float b0 = bias[col], b1 = bias[col + 1];
            float v00 = (acc[mi][ni][0] + b0) * scale;
            float v01 = (acc[mi][ni][1] + b1) * scale;
            float v10 = (acc[mi][ni][2] + b0) * scale;
            float v11 = (acc[mi][ni][3] + b1) * scale;
            if (head_layout) {
                int bb = row >> 11;
                int s  = row & (SL - 1);
                int hh = col >> 6;
                int d  = col & 63;
                size_t base = ((size_t)(bb * NH + hh)) * SL;
                *reinterpret_cast<float2*>(C + (base + s) * DK + d)     = make_float2(v00, v01);
                *reinterpret_cast<float2*>(C + (base + s + 8) * DK + d) = make_float2(v10, v11);
            } else {
                *reinterpret_cast<float2*>(C + (size_t)row * DM + col)       = make_float2(v00, v01);
                *reinterpret_cast<float2*>(C + (size_t)(row + 8) * DM + col) = make_float2(v10, v11);
            }
        }
    }
}

// ---------------------------------------------------------------------------
// Flash attention, TF32 tensor cores.
// Block: 256 threads (8 warps), 128 q-rows; warp owns 16 rows (row-complete).
// Streams keys in tiles of 64. P round-trips through smem (overlaid on sK).
// Q is pre-scaled by 1/sqrt(DK) in the Q projection.
// ---------------------------------------------------------------------------
#define KP_ST 68
#define V_ST  72
#define ATTN_SMEM_BYTES ((128 * KP_ST + 64 * V_ST) * 4 + 64 * 4)

__global__ __launch_bounds__(256, 2) void attn_tc(
    const float* __restrict__ Qh, const float* __restrict__ Kh,
    const float* __restrict__ Vh, const int* __restrict__ mask,
    float* __restrict__ outp)
{
    extern __shared__ float smem[];
    float* sKP = smem;                       // 128 x 68 (K tile in rows 0..63; P 128 rows)
    float* sV  = smem + 128 * KP_ST;         // 64 x 72
    int*  sMsk = (int*)(sV + 64 * V_ST);     // 64

    int bh = blockIdx.y;
    int b = bh / NH, h = bh - b * NH;
    int tid = threadIdx.x, lane = tid & 31, warp = tid >> 5;
    int rowBase = blockIdx.x << 7;

    const float* kbase = Kh + (size_t)bh * SL * DK;
    const float* vbase = Vh + (size_t)bh * SL * DK;
    const int*   mrow  = mask + b * SL;
    const float* qa = Qh + ((size_t)bh * SL + rowBase + warp * 16 + (lane >> 2)) * DK;
    const float* qb = qa + 8 * DK;

    float O[8][4];
    #pragma unroll
    for (int nt = 0; nt < 8; nt++)
        #pragma unroll
        for (int r = 0; r < 4; r++) O[nt][r] = 0.f;
    float m0 = -1e30f, m1 = -1e30f, l0 = 0.f, l1 = 0.f;

    float* sPw = sKP + (warp * 16) * KP_ST;  // this warp's P slice
    int pr = lane >> 2, pc = 2 * (lane & 3);

    for (int kt = 0; kt < SL; kt += 64) {
        __syncthreads();
        // Stage K (rows 0..63 of sKP) and V tiles, tf32-rounded.
        #pragma unroll
        for (int i = 0; i < 4; i++) {
            int idx = tid + (i << 8);
            int row = idx >> 4, c4 = (idx & 15) << 2;
            float4 kv = *reinterpret_cast<const float4*>(kbase + (size_t)(kt + row) * DK + c4);
            *reinterpret_cast<float4*>(sKP + row * KP_ST + c4) =
                make_float4(f2tf_f(kv.x), f2tf_f(kv.y), f2tf_f(kv.z), f2tf_f(kv.w));
            float4 vv = *reinterpret_cast<const float4*>(vbase + (size_t)(kt + row) * DK + c4);
            *reinterpret_cast<float4*>(sV + row * V_ST + c4) =
                make_float4(f2tf_f(vv.x), f2tf_f(vv.y), f2tf_f(vv.z), f2tf_f(vv.w));
        }
        if (tid < 64) sMsk[tid] = mrow[kt + tid];
        __syncthreads();

        // QK^T -> scores (Q already scaled by 1/8)
        float sc[8][4];
        #pragma unroll
        for (int nt = 0; nt < 8; nt++)
            #pragma unroll
            for (int r = 0; r < 4; r++) sc[nt][r] = 0.f;

        #pragma unroll
        for (int ks = 0; ks < 8; ks++) {
            int kk = (ks << 3) + (lane & 3);
            uint32_t a0 = f2tf(qa[kk]);
            uint32_t a1 = f2tf(qb[kk]);
            uint32_t a2 = f2tf(qa[kk + 4]);
            uint32_t a3 = f2tf(qb[kk + 4]);
            #pragma unroll
            for (int nt = 0; nt < 8; nt++) {
                int nn = nt * 8 + (lane >> 2);
                uint32_t b0 = __float_as_uint(sKP[nn * KP_ST + kk]);
                uint32_t b1 = __float_as_uint(sKP[nn * KP_ST + kk + 4]);
                mma_tf32(sc[nt], a0, a1, a2, a3, b0, b1);
            }
        }

        // Mask + row max (rows live entirely within a lane-quad)
        float mx0 = -1e30f, mx1 = -1e30f;
        #pragma unroll
        for (int nt = 0; nt < 8; nt++) {
            int c0 = nt * 8 + pc;
            bool u0 = sMsk[c0] != 0, u1 = sMsk[c0 + 1] != 0;
            sc[nt][0] = u0 ? sc[nt][0] : -1e9f;
            sc[nt][1] = u1 ? sc[nt][1] : -1e9f;
            sc[nt][2] = u0 ? sc[nt][2] : -1e9f;
            sc[nt][3] = u1 ? sc[nt][3] : -1e9f;
            mx0 = fmaxf(mx0, fmaxf(sc[nt][0], sc[nt][1]));
            mx1 = fmaxf(mx1, fmaxf(sc[nt][2], sc[nt][3]));
        }
        mx0 = fmaxf(mx0, __shfl_xor_sync(0xffffffffu, mx0, 1));
        mx0 = fmaxf(mx0, __shfl_xor_sync(0xffffffffu, mx0, 2));
        mx1 = fmaxf(mx1, __shfl_xor_sync(0xffffffffu, mx1, 1));
        mx1 = fmaxf(mx1, __shfl_xor_sync(0xffffffffu, mx1, 2));

        float nm0 = fmaxf(m0, mx0), nm1 = fmaxf(m1, mx1);
        float cor0 = __expf(m0 - nm0), cor1 = __expf(m1 - nm1);
        m0 = nm0; m1 = nm1;

        float ps0 = 0.f, ps1 = 0.f;
        #pragma unroll
        for (int nt = 0; nt < 8; nt++) {
            sc[nt][0] = __expf(sc[nt][0] - nm0);
            sc[nt][1] = __expf(sc[nt][1] - nm0);
            sc[nt][2] = __expf(sc[nt][2] - nm1);
            sc[nt][3] = __expf(sc[nt][3] - nm1);
            ps0 += sc[nt][0] + sc[nt][1];
            ps1 += sc[nt][2] + sc[nt][3];
        }
        ps0 += __shfl_xor_sync(0xffffffffu, ps0, 1);
        ps0 += __shfl_xor_sync(0xffffffffu, ps0, 2);
        ps1 += __shfl_xor_sync(0xffffffffu, ps1, 1);
        ps1 += __shfl_xor_sync(0xffffffffu, ps1, 2);
        l0 = l0 * cor0 + ps0;
        l1 = l1 * cor1 + ps1;
        #pragma unroll
        for (int nt = 0; nt < 8; nt++) {
            O[nt][0] *= cor0; O[nt][1] *= cor0;
            O[nt][2] *= cor1; O[nt][3] *= cor1;
        }

        __syncthreads();   // all warps done reading sK before P overwrites it

        // Write P (tf32-rounded) into this warp's sP slice
        #pragma unroll
        for (int nt = 0; nt < 8; nt++) {
            *reinterpret_cast<float2*>(sPw + pr * KP_ST + nt * 8 + pc) =
                make_float2(f2tf_f(sc[nt][0]), f2tf_f(sc[nt][1]));
            *reinterpret_cast<float2*>(sPw + (pr + 8) * KP_ST + nt * 8 + pc) =
                make_float2(f2tf_f(sc[nt][2]), f2tf_f(sc[nt][3]));
        }
        __syncwarp();

        // O += P @ V
        #pragma unroll
        for (int ks = 0; ks < 8; ks++) {
            int kk = (ks << 3) + (lane & 3);
            uint32_t a0 = __float_as_uint(sPw[pr * KP_ST + kk]);
            uint32_t a1 = __float_as_uint(sPw[(pr + 8) * KP_ST + kk]);
            uint32_t a2 = __float_as_uint(sPw[pr * KP_ST + kk + 4]);
            uint32_t a3 = __float_as_uint(sPw[(pr + 8) * KP_ST + kk + 4]);
            #pragma unroll
            for (int nt = 0; nt < 8; nt++) {
                int nn = nt * 8 + (lane >> 2);
                uint32_t b0 = __float_as_uint(sV[kk * V_ST + nn]);
                uint32_t b1 = __float_as_uint(sV[(kk + 4) * V_ST + nn]);
                mma_tf32(O[nt], a0, a1, a2, a3, b0, b1);
            }
        }
    }

    // Epilogue: normalize and store into [B, S, DM]
    float inv0 = 1.f / l0, inv1 = 1.f / l1;
    int srow = rowBase + warp * 16 + (lane >> 2);
    size_t obase = ((size_t)b * SL + srow) * DM + h * DK;
    #pragma unroll
    for (int nt = 0; nt < 8; nt++) {
        int col = nt * 8 + pc;
        *reinterpret_cast<float2*>(outp + obase + col) =
            make_float2(O[nt][0] * inv0, O[nt][1] * inv0);
        *reinterpret_cast<float2*>(outp + obase + (size_t)8 * DM + col) =
            make_float2(O[nt][2] * inv1, O[nt][3] * inv1);
    }
}

// ---------------------------------------------------------------------------
extern "C" void kernel_launch(void* const* d_in, const int* in_sizes, int n_in,
                              void* d_out, int out_size)
{
    const float* q  = (const float*)d_in[0];
    const float* k  = (const float*)d_in[1];
    const float* v  = (const float*)d_in[2];
    const float* Wq = (const float*)d_in[3];
    const float* bq = (const float*)d_in[4];
    const float* Wk = (const float*)d_in[5];
    const float* bk = (const float*)d_in[6];
    const float* Wv = (const float*)d_in[7];
    const float* bv = (const float*)d_in[8];
    const float* Wo = (const float*)d_in[9];
    const float* bo = (const float*)d_in[10];
    const int* mask = (const int*)d_in[11];

    float *Qh, *Kh, *Vh, *attn;
    cudaGetSymbolAddress((void**)&Qh,   g_Qh);
    cudaGetSymbolAddress((void**)&Kh,   g_Kh);
    cudaGetSymbolAddress((void**)&Vh,   g_Vh);
    cudaGetSymbolAddress((void**)&attn, g_attn);

    cudaFuncSetAttribute(attn_tc, cudaFuncAttributeMaxDynamicSharedMemorySize,
                         ATTN_SMEM_BYTES);

    dim3 gg(DM / 64, MR / 128);   // (12, 32)
    gemm_tc<<<gg, 256>>>(q, Wq, bq, Qh, 1, 0.125f);   // Q pre-scaled by 1/sqrt(DK)
    gemm_tc<<<gg, 256>>>(k, Wk, bk, Kh, 1, 1.0f);
    gemm_tc<<<gg, 256>>>(v, Wv, bv, Vh, 1, 1.0f);

    attn_tc<<<dim3(SL / 128, BH), 256, ATTN_SMEM_BYTES>>>(Qh, Kh, Vh, mask, attn);

    gemm_tc<<<gg, 256>>>(attn, Wo, bo, (float*)d_out, 0, 1.0f);
}

// round 8
// speedup vs baseline: 3.7799x; 1.1193x over previous
#include <cuda_runtime.h>
#include <cuda_bf16.h>
#include <cstdint>

#define DM 768
#define NH 12
#define DK 64
#define NB 2
#define SL 2048
#define MR (NB*SL)     // 4096
#define BH (NB*NH)     // 24

// Scratch (allocation-free requirement). Packed tf32 fragment-pair layouts.
__device__ float g_Qp[(size_t)BH*SL*DK];
__device__ float g_Kp[(size_t)BH*SL*DK];
__device__ float g_Vp[(size_t)BH*SL*DK];
__device__ float g_attn[(size_t)MR*DM];

// ---------------------------------------------------------------------------
__device__ __forceinline__ uint32_t f2tf(float x) {
    uint32_t r; asm("cvt.rna.tf32.f32 %0, %1;" : "=r"(r) : "f"(x)); return r;
}
__device__ __forceinline__ float f2tf_f(float x) {
    return __uint_as_float(f2tf(x));
}
__device__ __forceinline__ void mma_tf32(float c[4],
    uint32_t a0, uint32_t a1, uint32_t a2, uint32_t a3,
    uint32_t b0, uint32_t b1)
{
    asm volatile(
        "mma.sync.aligned.m16n8k8.row.col.f32.tf32.tf32.f32 "
        "{%0,%1,%2,%3}, {%4,%5,%6,%7}, {%8,%9}, {%0,%1,%2,%3};"
        : "+f"(c[0]), "+f"(c[1]), "+f"(c[2]), "+f"(c[3])
        : "r"(a0), "r"(a1), "r"(a2), "r"(a3), "r"(b0), "r"(b1));
}

#define CP_ASYNC16(dst, src) \
    asm volatile("cp.async.cg.shared.global [%0], [%1], 16;" :: "r"(dst), "l"(src))
#define CP_COMMIT() asm volatile("cp.async.commit_group;")
#define CP_WAIT0()  asm volatile("cp.async.wait_group 0;")

// ---------------------------------------------------------------------------
// GEMM: C[M,768] = (A[M,768] @ W[768,768] + bias) * scale
// 128x64 block tile, kTile 32, 256 threads. Pair-packed smem (float2 holds
// {x[k], x[k+4]}) -> LDS.64 fragment loads. Register prefetch of next k-tile.
// mode: 0 = plain fp32 [M,DM];  1/2/3 = tf32-rounded packed Q/K/V layouts.
// ---------------------------------------------------------------------------
#define GAST 20    // float2 stride of sA row (16 pairs + 4 pad)
#define GWST 68    // float2 stride of sW slot-row (64 + 4 pad)

__global__ __launch_bounds__(256, 2) void gemm_tc(
    const float* __restrict__ A, const float* __restrict__ W,
    const float* __restrict__ bias, float* __restrict__ C,
    int mode, float scale)
{
    __shared__ float2 sA[128 * GAST];
    __shared__ float2 sW[16 * GWST];

    int tid = threadIdx.x, lane = tid & 31, warp = tid >> 5;
    int wm = warp & 3, wn = warp >> 2;
    int q = lane >> 2, r = lane & 3;
    int mBase = blockIdx.y << 7, nBase = blockIdx.x << 6;

    // staging unit assignments
    int ur0 = tid >> 2,        uo0 = tid & 3;        // A unit 0: row, octet
    int ur1 = ur0 + 64;                              // A unit 1 (tid+256)
    int wslot = tid >> 4, wn4 = (tid & 15) << 2;     // W unit
    int wkk = ((wslot >> 2) << 3) + (wslot & 3);

    const float* Ab = A + (size_t)mBase * DM;

    float4 pa00, pa01, pa10, pa11, pw0, pw1;
    pa00 = *(const float4*)(Ab + (size_t)ur0 * DM + uo0 * 8);
    pa01 = *(const float4*)(Ab + (size_t)ur0 * DM + uo0 * 8 + 4);
    pa10 = *(const float4*)(Ab + (size_t)ur1 * DM + uo0 * 8);
    pa11 = *(const float4*)(Ab + (size_t)ur1 * DM + uo0 * 8 + 4);
    pw0  = *(const float4*)(W + (size_t)wkk * DM + nBase + wn4);
    pw1  = *(const float4*)(W + (size_t)(wkk + 4) * DM + nBase + wn4);

    float acc[2][4][4];
    #pragma unroll
    for (int mi = 0; mi < 2; mi++)
        #pragma unroll
        for (int ni = 0; ni < 4; ni++)
            #pragma unroll
            for (int t = 0; t < 4; t++) acc[mi][ni][t] = 0.f;

    for (int k0 = 0; k0 < DM; k0 += 32) {
        // cvt + STS (pair-packed)
        {
            float2* d = sA + ur0 * GAST + (uo0 << 2);
            d[0] = make_float2(f2tf_f(pa00.x), f2tf_f(pa01.x));
            d[1] = make_float2(f2tf_f(pa00.y), f2tf_f(pa01.y));
            d[2] = make_float2(f2tf_f(pa00.z), f2tf_f(pa01.z));
            d[3] = make_float2(f2tf_f(pa00.w), f2tf_f(pa01.w));
            float2* e = sA + ur1 * GAST + (uo0 << 2);
            e[0] = make_float2(f2tf_f(pa10.x), f2tf_f(pa11.x));
            e[1] = make_float2(f2tf_f(pa10.y), f2tf_f(pa11.y));
            e[2] = make_float2(f2tf_f(pa10.z), f2tf_f(pa11.z));
            e[3] = make_float2(f2tf_f(pa10.w), f2tf_f(pa11.w));
            float2* f = sW + wslot * GWST + wn4;
            f[0] = make_float2(f2tf_f(pw0.x), f2tf_f(pw1.x));
            f[1] = make_float2(f2tf_f(pw0.y), f2tf_f(pw1.y));
            f[2] = make_float2(f2tf_f(pw0.z), f2tf_f(pw1.z));
            f[3] = make_float2(f2tf_f(pw0.w), f2tf_f(pw1.w));
        }
        __syncthreads();

        // prefetch next k-tile into registers (overlaps with mma below)
        if (k0 + 32 < DM) {
            const float* Ak = Ab + k0 + 32;
            pa00 = *(const float4*)(Ak + (size_t)ur0 * DM + uo0 * 8);
            pa01 = *(const float4*)(Ak + (size_t)ur0 * DM + uo0 * 8 + 4);
            pa10 = *(const float4*)(Ak + (size_t)ur1 * DM + uo0 * 8);
            pa11 = *(const float4*)(Ak + (size_t)ur1 * DM + uo0 * 8 + 4);
            const float* Wk = W + (size_t)(k0 + 32) * DM + nBase + wn4;
            pw0 = *(const float4*)(Wk + (size_t)wkk * DM);
            pw1 = *(const float4*)(Wk + (size_t)(wkk + 4) * DM);
        }

        #pragma unroll
        for (int ks = 0; ks < 4; ks++) {
            int kp = (ks << 2) + r;
            float2 aL0 = sA[(wm * 32 + q) * GAST + kp];
            float2 aH0 = sA[(wm * 32 + 8 + q) * GAST + kp];
            float2 aL1 = sA[(wm * 32 + 16 + q) * GAST + kp];
            float2 aH1 = sA[(wm * 32 + 24 + q) * GAST + kp];
            float2 bb[4];
            #pragma unroll
            for (int ni = 0; ni < 4; ni++)
                bb[ni] = sW[kp * GWST + wn * 32 + ni * 8 + q];
            #pragma unroll
            for (int ni = 0; ni < 4; ni++)
                mma_tf32(acc[0][ni],
                    __float_as_uint(aL0.x), __float_as_uint(aH0.x),
                    __float_as_uint(aL0.y), __float_as_uint(aH0.y),
                    __float_as_uint(bb[ni].x), __float_as_uint(bb[ni].y));
            #pragma unroll
            for (int ni = 0; ni < 4; ni++)
                mma_tf32(acc[1][ni],
                    __float_as_uint(aL1.x), __float_as_uint(aH1.x),
                    __float_as_uint(aL1.y), __float_as_uint(aH1.y),
                    __float_as_uint(bb[ni].x), __float_as_uint(bb[ni].y));
        }
        __syncthreads();
    }

    // Epilogue
    #pragma unroll
    for (int mi = 0; mi < 2; mi++) {
        int row = mBase + wm * 32 + mi * 16 + q;
        #pragma unroll
        for (int ni = 0; ni < 4; ni++) {
            int col = nBase + wn * 32 + ni * 8 + 2 * r;
            float b0 = bias[col], b1 = bias[col + 1];
            float v00 = (acc[mi][ni][0] + b0) * scale;
            float v01 = (acc[mi][ni][1] + b1) * scale;
            float v10 = (acc[mi][ni][2] + b0) * scale;
            float v11 = (acc[mi][ni][3] + b1) * scale;
            if (mode == 0) {
                *reinterpret_cast<float2*>(C + (size_t)row * DM + col)       = make_float2(v00, v01);
                *reinterpret_cast<float2*>(C + (size_t)(row + 8) * DM + col) = make_float2(v10, v11);
            } else {
                v00 = f2tf_f(v00); v01 = f2tf_f(v01);
                v10 = f2tf_f(v10); v11 = f2tf_f(v11);
                int bb = row >> 11, s = row & (SL - 1);
                int hh = col >> 6,  d = col & 63;
                int bh = bb * NH + hh;
                if (mode == 1) {          // Q: [(bh,s)][kp]{comp}
                    size_t base = ((size_t)bh * SL + s) * 64
                                + (size_t)(((d >> 3) << 2) + (d & 3)) * 2 + ((d >> 2) & 1);
                    C[base] = v00;            C[base + 2] = v01;
                    C[base + 8 * 64] = v10;   C[base + 8 * 64 + 2] = v11;
                } else if (mode == 2) {   // K: [(bh,t)][n=s&63][kp]{comp}
                    int t = s >> 6, n = s & 63;
                    size_t base = (((size_t)bh * 32 + t) * 64 + n) * 64
                                + (size_t)(((d >> 3) << 2) + (d & 3)) * 2 + ((d >> 2) & 1);
                    C[base] = v00;            C[base + 2] = v01;
                    C[base + 8 * 64] = v10;   C[base + 8 * 64 + 2] = v11;
                } else {                  // V: [(bh,t)][vr][n=d]{comp}
                    int t = s >> 6, srow = s & 63;
                    int vr = ((srow >> 3) << 2) + (srow & 3);
                    int comp = (srow >> 2) & 1;
                    size_t base = (((size_t)bh * 32 + t) * 32 + vr) * 128 + (size_t)d * 2 + comp;
                    C[base] = v00;              C[base + 2] = v01;
                    C[base + 4 * 128] = v10;    C[base + 4 * 128 + 2] = v11;
                }
            }
        }
    }
}

// ---------------------------------------------------------------------------
// Flash attention, TF32, cp.async double-buffered K/V/mask, packed fragments.
// Block: 256 threads (8 warps), 128 q-rows; warp owns 16 rows.
// ---------------------------------------------------------------------------
#define KST 36   // float2 stride per K n-row (32 + 4 pad)
#define VST 68   // float2 stride per V vr-row (64 + 4 pad)
#define PST 68   // float stride per P row (64 + 4 pad)
#define SK_F2 (2 * 64 * KST)
#define SV_F2 (2 * 32 * VST)
#define SP_F  (128 * PST)
#define ATTN_SMEM_BYTES (SK_F2 * 8 + SV_F2 * 8 + SP_F * 4 + 2 * 64 * 4)

__device__ __forceinline__ void stage_tile(
    const float4* ksrc, const float4* vsrc, const int* msrc,
    uint32_t kdst, uint32_t vdst, uint32_t mdst, int tid)
{
    #pragma unroll
    for (int i = 0; i < 4; i++) {
        int idx = tid + (i << 8);
        int n  = idx >> 4, kp = (idx & 15) << 1;
        CP_ASYNC16(kdst + (uint32_t)(n * KST + kp) * 8, ksrc + idx);
        int vr = idx >> 5, nn = (idx & 31) << 1;
        CP_ASYNC16(vdst + (uint32_t)(vr * VST + nn) * 8, vsrc + idx);
    }
    if (tid < 16) CP_ASYNC16(mdst + (uint32_t)tid * 16, msrc + tid * 4);
    CP_COMMIT();
}

__global__ __launch_bounds__(256, 2) void attn_tc(
    const float* __restrict__ Qp, const float* __restrict__ Kp,
    const float* __restrict__ Vp, const int* __restrict__ mask,
    float* __restrict__ outp)
{
    extern __shared__ char smem_raw[];
    float2* sK = (float2*)smem_raw;
    float2* sV = sK + SK_F2;
    float*  sP = (float*)(sV + SV_F2);
    int*    sM = (int*)(sP + SP_F);

    int bh = blockIdx.y;
    int b = bh / NH, h = bh - b * NH;
    int tid = threadIdx.x, lane = tid & 31, warp = tid >> 5;
    int q = lane >> 2, r = lane & 3;
    int rowBase = blockIdx.x << 7;

    const float4* kTiles = (const float4*)Kp + (size_t)bh * 32 * 1024;
    const float4* vTiles = (const float4*)Vp + (size_t)bh * 32 * 1024;
    const int*    mrow   = mask + b * SL;
    const float2* qpA = (const float2*)Qp + ((size_t)bh * SL + rowBase + warp * 16 + q) * 32;
    const float2* qpB = qpA + 8 * 32;

    uint32_t sKa = (uint32_t)__cvta_generic_to_shared(sK);
    uint32_t sVa = (uint32_t)__cvta_generic_to_shared(sV);
    uint32_t sMa = (uint32_t)__cvta_generic_to_shared(sM);

    float O[8][4];
    #pragma unroll
    for (int nt = 0; nt < 8; nt++)
        #pragma unroll
        for (int t = 0; t < 4; t++) O[nt][t] = 0.f;
    float m0 = -1e30f, m1 = -1e30f, l0 = 0.f, l1 = 0.f;

    float* sPw = sP + (warp * 16) * PST;

    stage_tile(kTiles, vTiles, mrow, sKa, sVa, sMa, tid);

    for (int t = 0; t < 32; t++) {
        int buf = t & 1;
        CP_WAIT0();
        __syncthreads();
        if (t < 31)
            stage_tile(kTiles + (size_t)(t + 1) * 1024,
                       vTiles + (size_t)(t + 1) * 1024,
                       mrow + (t + 1) * 64,
                       sKa + (uint32_t)((buf ^ 1) * 64 * KST) * 8,
                       sVa + (uint32_t)((buf ^ 1) * 32 * VST) * 8,
                       sMa + (uint32_t)((buf ^ 1) * 64) * 4, tid);

        const float2* Kb = sK + buf * 64 * KST;
        const float2* Vb = sV + buf * 32 * VST;
        const int*    Mb = sM + buf * 64;

        // ---- QK^T ----
        float sc[8][4];
        #pragma unroll
        for (int nt = 0; nt < 8; nt++)
            #pragma unroll
            for (int x = 0; x < 4; x++) sc[nt][x] = 0.f;

        #pragma unroll
        for (int ks = 0; ks < 8; ks++) {
            int kp = (ks << 2) + r;
            float2 qA = qpA[kp];
            float2 qB = qpB[kp];
            uint32_t a0 = __float_as_uint(qA.x), a1 = __float_as_uint(qB.x);
            uint32_t a2 = __float_as_uint(qA.y), a3 = __float_as_uint(qB.y);
            #pragma unroll
            for (int nt = 0; nt < 8; nt++) {
                float2 bb = Kb[(nt * 8 + q) * KST + kp];
                mma_tf32(sc[nt], a0, a1, a2, a3,
                         __float_as_uint(bb.x), __float_as_uint(bb.y));
            }
        }

        // ---- mask + online softmax ----
        int pc = 2 * r;
        float mx0 = -1e30f, mx1 = -1e30f;
        #pragma unroll
        for (int nt = 0; nt < 8; nt++) {
            int2 mk = *reinterpret_cast<const int2*>(&Mb[nt * 8 + pc]);
            bool u0 = mk.x != 0, u1 = mk.y != 0;
            sc[nt][0] = u0 ? sc[nt][0] : -1e9f;
            sc[nt][1] = u1 ? sc[nt][1] : -1e9f;
            sc[nt][2] = u0 ? sc[nt][2] : -1e9f;
            sc[nt][3] = u1 ? sc[nt][3] : -1e9f;
            mx0 = fmaxf(mx0, fmaxf(sc[nt][0], sc[nt][1]));
            mx1 = fmaxf(mx1, fmaxf(sc[nt][2], sc[nt][3]));
        }
        mx0 = fmaxf(mx0, __shfl_xor_sync(0xffffffffu, mx0, 1));
        mx0 = fmaxf(mx0, __shfl_xor_sync(0xffffffffu, mx0, 2));
        mx1 = fmaxf(mx1, __shfl_xor_sync(0xffffffffu, mx1, 1));
        mx1 = fmaxf(mx1, __shfl_xor_sync(0xffffffffu, mx1, 2));

        float nm0 = fmaxf(m0, mx0), nm1 = fmaxf(m1, mx1);
        float cor0 = __expf(m0 - nm0), cor1 = __expf(m1 - nm1);
        m0 = nm0; m1 = nm1;

        float ps0 = 0.f, ps1 = 0.f;
        #pragma unroll
        for (int nt = 0; nt < 8; nt++) {
            sc[nt][0] = __expf(sc[nt][0] - nm0);
            sc[nt][1] = __expf(sc[nt][1] - nm0);
            sc[nt][2] = __expf(sc[nt][2] - nm1);
            sc[nt][3] = __expf(sc[nt][3] - nm1);
            ps0 += sc[nt][0] + sc[nt][1];
            ps1 += sc[nt][2] + sc[nt][3];
        }
        ps0 += __shfl_xor_sync(0xffffffffu, ps0, 1);
        ps0 += __shfl_xor_sync(0xffffffffu, ps0, 2);
        ps1 += __shfl_xor_sync(0xffffffffu, ps1, 1);
        ps1 += __shfl_xor_sync(0xffffffffu, ps1, 2);
        l0 = l0 * cor0 + ps0;
        l1 = l1 * cor1 + ps1;
        #pragma unroll
        for (int nt = 0; nt < 8; nt++) {
            O[nt][0] *= cor0; O[nt][1] *= cor0;
            O[nt][2] *= cor1; O[nt][3] *= cor1;
        }

        // ---- write P (per-warp private buffer; no block barrier needed) ----
        #pragma unroll
        for (int nt = 0; nt < 8; nt++) {
            *reinterpret_cast<float2*>(sPw + q * PST + nt * 8 + pc) =
                make_float2(f2tf_f(sc[nt][0]), f2tf_f(sc[nt][1]));
            *reinterpret_cast<float2*>(sPw + (q + 8) * PST + nt * 8 + pc) =
                make_float2(f2tf_f(sc[nt][2]), f2tf_f(sc[nt][3]));
        }
        __syncwarp();

        // ---- O += P @ V ----
        #pragma unroll
        for (int ks = 0; ks < 8; ks++) {
            int kk = (ks << 3) + r;
            uint32_t a0 = __float_as_uint(sPw[q * PST + kk]);
            uint32_t a1 = __float_as_uint(sPw[(q + 8) * PST + kk]);
            uint32_t a2 = __float_as_uint(sPw[q * PST + kk + 4]);
            uint32_t a3 = __float_as_uint(sPw[(q + 8) * PST + kk + 4]);
            #pragma unroll
            for (int nt = 0; nt < 8; nt++) {
                float2 vv = Vb[((ks << 2) + r) * VST + nt * 8 + q];
                mma_tf32(O[nt], a0, a1, a2, a3,
                         __float_as_uint(vv.x), __float_as_uint(vv.y));
            }
        }
    }

    // ---- epilogue ----
    float inv0 = 1.f / l0, inv1 = 1.f / l1;
    int srow = rowBase + warp * 16 + q;
    size_t obase = ((size_t)b * SL + srow) * DM + h * DK;
    #pragma unroll
    for (int nt = 0; nt < 8; nt++) {
        int col = nt * 8 + 2 * r;
        *reinterpret_cast<float2*>(outp + obase + col) =
            make_float2(O[nt][0] * inv0, O[nt][1] * inv0);
        *reinterpret_cast<float2*>(outp + obase + (size_t)8 * DM + col) =
            make_float2(O[nt][2] * inv1, O[nt][3] * inv1);
    }
}

// ---------------------------------------------------------------------------
extern "C" void kernel_launch(void* const* d_in, const int* in_sizes, int n_in,
                              void* d_out, int out_size)
{
    const float* q  = (const float*)d_in[0];
    const float* k  = (const float*)d_in[1];
    const float* v  = (const float*)d_in[2];
    const float* Wq = (const float*)d_in[3];
    const float* bq = (const float*)d_in[4];
    const float* Wk = (const float*)d_in[5];
    const float* bk = (const float*)d_in[6];
    const float* Wv = (const float*)d_in[7];
    const float* bv = (const float*)d_in[8];
    const float* Wo = (const float*)d_in[9];
    const float* bo = (const float*)d_in[10];
    const int* mask = (const int*)d_in[11];

    float *Qp, *Kp, *Vp, *attn;
    cudaGetSymbolAddress((void**)&Qp,   g_Qp);
    cudaGetSymbolAddress((void**)&Kp,   g_Kp);
    cudaGetSymbolAddress((void**)&Vp,   g_Vp);
    cudaGetSymbolAddress((void**)&attn, g_attn);

    cudaFuncSetAttribute(attn_tc, cudaFuncAttributeMaxDynamicSharedMemorySize,
                         ATTN_SMEM_BYTES);

    dim3 gg(DM / 64, MR / 128);   // (12, 32)
    gemm_tc<<<gg, 256>>>(q, Wq, bq, Qp, 1, 0.125f);   // Q pre-scaled by 1/sqrt(DK)
    gemm_tc<<<gg, 256>>>(k, Wk, bk, Kp, 2, 1.0f);
    gemm_tc<<<gg, 256>>>(v, Wv, bv, Vp, 3, 1.0f);

    attn_tc<<<dim3(SL / 128, BH), 256, ATTN_SMEM_BYTES>>>(Qp, Kp, Vp, mask, attn);

    gemm_tc<<<gg, 256>>>(attn, Wo, bo, (float*)d_out, 0, 1.0f);
}